// round 17
// baseline (speedup 1.0000x reference)
#include <cuda_runtime.h>
#include <math.h>

#define HH 512
#define WW 512
#define PLANE (512*512)
#define SHAPE_OFF (1*PLANE)
#define SIZE_OFF  (1025*PLANE)
#define HEAT_OFF  (1027*PLANE)
#define NPTS 10
#define MM 128
#define BLKS_PER_HM 32

// per-block partial argmax results; every slot written every run -> no init
__device__ unsigned long long g_partial[NPTS][BLKS_PER_HM];

__device__ __forceinline__ unsigned int fkey(float v) {
    unsigned int b = __float_as_uint(v);
    return (b & 0x80000000u) ? ~b : (b | 0x80000000u);
}
__device__ __forceinline__ unsigned long long umax64(unsigned long long a,
                                                     unsigned long long b) {
    return a > b ? a : b;
}

// 320 blocks (32/heatmap) x 256 threads; 32 floats/thread via 8x float4.
// (R14 geometry - measured best.)
__global__ void __launch_bounds__(256) argmax_kernel(const float* __restrict__ feat) {
    int hm    = blockIdx.x >> 5;
    int chunk = blockIdx.x & 31;
    const float* heat = feat + HEAT_OFF + (size_t)hm * PLANE;
    int base = chunk * 8192;
    int tid = threadIdx.x;

    float bestv = -__int_as_float(0x7F800000);  // -inf
    int   bestq = base;
    float4 bq = make_float4(bestv, bestv, bestv, bestv);

#pragma unroll
    for (int j = 0; j < 8; j++) {
        int e = base + ((j * 256 + tid) << 2);
        float4 v = *reinterpret_cast<const float4*>(heat + e);
        float m = fmaxf(fmaxf(v.x, v.y), fmaxf(v.z, v.w));
        // strict > : on ties the EARLIER quad is kept (e strictly increases)
        if (m > bestv) { bestv = m; bestq = e; bq = v; }
    }

    // first element in winning quad equal to bestv -> global first occurrence
    int off4 = (bq.x == bestv) ? 0 : (bq.y == bestv) ? 1 : (bq.z == bestv) ? 2 : 3;
    int bestidx = bestq + off4;

    unsigned long long best =
        ((unsigned long long)fkey(bestv) << 32) |
        (unsigned int)(~(unsigned int)bestidx);

#pragma unroll
    for (int off = 16; off > 0; off >>= 1)
        best = umax64(best, __shfl_xor_sync(0xFFFFFFFFu, best, off));

    __shared__ unsigned long long s[8];
    if ((tid & 31) == 0) s[tid >> 5] = best;
    __syncthreads();
    if (tid < 32) {
        unsigned long long v = (tid < 8) ? s[tid] : 0ULL;
#pragma unroll
        for (int off = 4; off > 0; off >>= 1)
            v = umax64(v, __shfl_xor_sync(0xFFFFFFFFu, v, off));
        if (tid == 0) g_partial[hm][chunk] = v;
    }
}

// grid (NPTS, 64) x 256: 8 independent warps per block, ZERO barriers/smem.
// Warp = 32 columns of one output row. Each warp: redundant partial reduce
// (speculative sizes overlapped) -> vec row in registers -> shuffles for
// x-interp -> sigmoid * saliency -> coalesced store.
__global__ void __launch_bounds__(256) compute_kernel(const float* __restrict__ feat,
                                                      float* __restrict__ out) {
    int pt   = blockIdx.x;
    int lane = threadIdx.x & 31;
    int wid  = threadIdx.x >> 5;          // 0..7

    // ---- per-warp meta resolution (no cross-warp dependency) ----
    unsigned long long v = g_partial[pt][lane];
    int idxj = (int)(~(unsigned int)(v & 0xFFFFFFFFu));
    // speculative size loads for MY candidate, in flight during the reduce
    float hv = fabsf(feat[SIZE_OFF + idxj]);
    float wv = fabsf(feat[SIZE_OFF + PLANE + idxj]);
    unsigned long long m = v;
#pragma unroll
    for (int off = 16; off > 0; off >>= 1)
        m = umax64(m, __shfl_xor_sync(0xFFFFFFFFu, m, off));
    // winner lane broadcasts its h/w/idx (keys unique -> exactly one winner)
    unsigned int wlane_mask = __ballot_sync(0xFFFFFFFFu, v == m);
    int wlane = __ffs(wlane_mask) - 1;
    int pbase = __shfl_sync(0xFFFFFFFFu, idxj, wlane);
    float hvw = __shfl_sync(0xFFFFFFFFu, hv, wlane);
    float wvw = __shfl_sync(0xFFFFFFFFu, wv, wlane);
    int h = min(max((int)hvw, 1), MM);
    int w = min(max((int)wvw, 1), MM);
    float hf = (float)h, wf = (float)w;
    int py = pbase >> 9;
    int px = pbase & 511;

    int r = blockIdx.y * 2 + (wid >> 2);       // output row
    int c = ((wid & 3) << 5) + lane;           // output column

    // y coordinate (uniform over warp)
    float sy = ((float)r + 0.5f) * 32.0f / hf - 0.5f;
    sy = fminf(fmaxf(sy, 0.0f), 31.0f);
    int y0 = (int)floorf(sy);
    int y1 = min(y0 + 1, 31);
    float wy = sy - (float)y0;

    // three independent loads issued together
    int gr = py - (h >> 1) + r;
    int gc = px - (w >> 1) + c;
    bool valid = (r < h) && (c < w) &&
                 (gr >= 0) && (gr < HH) && (gc >= 0) && (gc < WW);
    float sal = valid ? feat[gr * WW + gc] : 0.0f;
    float v0 = feat[SHAPE_OFF + (size_t)(y0 * 32 + lane) * PLANE + pbase];
    float v1 = feat[SHAPE_OFF + (size_t)(y1 * 32 + lane) * PLANE + pbase];

    // y-interp: lane holds row value for column index == lane
    float rowv = v0 * (1.0f - wy) + v1 * wy;

    // x-interp via shuffles (row lives in registers across the warp)
    float sx = ((float)c + 0.5f) * 32.0f / wf - 0.5f;
    sx = fminf(fmaxf(sx, 0.0f), 31.0f);
    int x0 = (int)floorf(sx);
    int x1 = min(x0 + 1, 31);
    float wx = sx - (float)x0;
    float a = __shfl_sync(0xFFFFFFFFu, rowv, x0);
    float b = __shfl_sync(0xFFFFFFFFu, rowv, x1);
    float val = a * (1.0f - wx) + b * wx;
    float lv = 1.0f / (1.0f + __expf(-val));

    out[(size_t)pt * (MM * MM) + (size_t)r * MM + c] = valid ? lv * sal : 0.0f;
}

extern "C" void kernel_launch(void* const* d_in, const int* in_sizes, int n_in,
                              void* d_out, int out_size) {
    const float* feat = (const float*)d_in[0];
    float* out = (float*)d_out;
    argmax_kernel<<<NPTS * BLKS_PER_HM, 256>>>(feat);
    dim3 g(NPTS, MM / 2);
    compute_kernel<<<g, 256>>>(feat, out);
}